// round 17
// baseline (speedup 1.0000x reference)
#include <cuda_runtime.h>
#include <cuda_fp16.h>
#include <cstdint>

#define W_DIM   21504
#define NSEG    64
#define NELEM   8192
#define TILE_R  64
#define MAX_TILES 192
#define TPB     256
#define SEG_U2  5376        // uint2 fp16 fragments per segment
#define PRE_Q   1344        // items per pre-block (SEG_U2/4)

// ---------------- device globals ----------------
__device__ int  d_starts[NSEG + 1];
__device__ int2 d_tiles[MAX_TILES];
__device__ int  d_ntiles;
__device__ __align__(16) uint2 d_wf[NSEG * SEG_U2];  // mma-fragment-ordered fp16 weights

// ---------------- wrappers ----------------
__device__ __forceinline__ void ldsm4(uint32_t* r, unsigned addr) {
    asm volatile("ldmatrix.sync.aligned.m8n8.x4.shared.b16 {%0,%1,%2,%3}, [%4];"
                 : "=r"(r[0]), "=r"(r[1]), "=r"(r[2]), "=r"(r[3]) : "r"(addr));
}
__device__ __forceinline__ void mma_f16(float* c, const uint32_t* a,
                                        uint32_t b0, uint32_t b1) {
    asm volatile("mma.sync.aligned.m16n8k16.row.col.f32.f16.f16.f32 "
                 "{%0,%1,%2,%3}, {%4,%5,%6,%7}, {%8,%9}, {%0,%1,%2,%3};"
                 : "+f"(c[0]), "+f"(c[1]), "+f"(c[2]), "+f"(c[3])
                 : "r"(a[0]), "r"(a[1]), "r"(a[2]), "r"(a[3]), "r"(b0), "r"(b1));
}
__device__ __forceinline__ uint32_t packh(float a, float b) {
    __half2 h = __floats2half2_rn(a, b);    // .x = a = low half (even k)
    return *reinterpret_cast<uint32_t*>(&h);
}
__device__ __forceinline__ void sts128(unsigned a, uint32_t x, uint32_t y,
                                       uint32_t z, uint32_t w) {
    asm volatile("st.shared.v4.b32 [%0], {%1,%2,%3,%4};"
                 :: "r"(a), "r"(x), "r"(y), "r"(z), "r"(w));
}
__device__ __forceinline__ unsigned smem_u32(const void* p) {
    unsigned a;
    asm("{ .reg .u64 t; cvta.to.shared.u64 t, %1; cvt.u32.u64 %0, t; }"
        : "=r"(a) : "l"(p));
    return a;
}

// ---------------- prekernel: direct-gather fp16 fragments + scan ------------
__global__ void pre_kernel(const int* __restrict__ counts,
                           const float* __restrict__ w) {
    if (blockIdx.x == 4 * NSEG) {
        __shared__ int wsum[2], wtsum[2];
        const int t = threadIdx.x;
        int c = 0, nt = 0, sc = 0, st = 0;
        if (t < 64) {
            c  = counts[t];
            nt = (c + TILE_R - 1) >> 6;
            sc = c; st = nt;
            #pragma unroll
            for (int d = 1; d < 32; d <<= 1) {
                int a = __shfl_up_sync(0xffffffffu, sc, d);
                int b = __shfl_up_sync(0xffffffffu, st, d);
                if ((t & 31) >= d) { sc += a; st += b; }
            }
            if ((t & 31) == 31) { wsum[t >> 5] = sc; wtsum[t >> 5] = st; }
        }
        __syncthreads();
        if (t < 64) {
            if (t >= 32) { sc += wsum[0]; st += wtsum[0]; }
            const int startc = sc - c;
            const int startt = st - nt;
            d_starts[t] = startc;
            if (t == 63) { d_starts[NSEG] = sc; d_ntiles = st; }
            for (int k = 0; k < nt; k++)
                d_tiles[startt + k] = make_int2(startc + TILE_R * k, t);
        }
        return;
    }
    // Each w element feeds exactly one fragment -> direct gather, no staging.
    const int g = blockIdx.x >> 2;
    const int q = blockIdx.x & 3;
    const float* wg = w + (size_t)g * W_DIM;
    uint2* dst = d_wf + (size_t)g * SEG_U2;
    const int end = (q + 1) * PRE_Q;
    for (int it = q * PRE_Q + threadIdx.x; it < end; it += 256) {
        int MUL, KS, WOFF, base; float coeff; int rem;
        if (it < 4096)      { MUL=128; KS=8; WOFF=0;     base=0;    coeff=0.011048543456039806f; rem=it; }
        else if (it < 5120) { MUL=64;  KS=4; WOFF=16384; base=4096; coeff=0.015625f;             rem=it-4096; }
        else                { MUL=32;  KS=2; WOFF=20480; base=5120; coeff=0.022097086912079613f; rem=it-5120; }
        const int lane = rem & 31;
        const int fr   = rem >> 5;
        const int ks   = fr % KS;
        const int nbl  = fr / KS;
        const int o    = nbl * 8 + (lane >> 2);
        const int m0   = ks * 16 + (lane & 3) * 2;
        const float* wb = wg + WOFF + o;
        uint32_t b0 = packh(coeff * __ldg(&wb[(m0)     * MUL]),
                            coeff * __ldg(&wb[(m0 + 1) * MUL]));
        uint32_t b1 = packh(coeff * __ldg(&wb[(m0 + 8) * MUL]),
                            coeff * __ldg(&wb[(m0 + 9) * MUL]));
        dst[base + fr * 32 + lane] = make_uint2(b0, b1);
    }
}

// ---------------- main: single-fp16 mma per 64-row tile ----------------
// GEMM per tile: M' = 64*DIM, N = K = MUL.  A[(r*DIM+i)][m] = fp16(x[r][m][i])
// Warp grid: WMG M-groups x WNG N-groups (WMG*WNG = 8).
template <int MUL, int DIM, int IOFF2, int WMG, int WNG>
__device__ __forceinline__ void run_irrep(const float* __restrict__ x,
                                          float* __restrict__ y,
                                          int tile, char* smraw) {
    constexpr int K   = MUL;
    constexpr int CH  = MUL * DIM;
    constexpr int LD  = K + 8;             // A row stride (fp16)
    constexpr int WM  = 64 * DIM / 16 / WMG;   // m16 tiles per warp
    constexpr int NBW = MUL / WNG / 8;         // n8 blocks per warp
    constexpr int KS  = MUL / 16;
    constexpr int LDC = MUL + 2;           // C smem row stride (floats)

    float* Cs = reinterpret_cast<float*>(smraw);

    const int2 tt  = d_tiles[tile];
    const int row0 = tt.x;
    const int g    = tt.y;
    int nrows = d_starts[g + 1] - row0;
    if (nrows > TILE_R) nrows = TILE_R;

    const unsigned sbase = smem_u32(smraw);
    const int tid = threadIdx.x;

    // ---- stage A: x -> fp16, row-major [rowp][k] ----
    const float* xt = x + (size_t)row0 * CH;
    constexpr int IPR = K / 8;
    for (int e = tid; e < TILE_R * IPR; e += TPB) {
        const int r  = e / IPR;
        const int m0 = (e - r * IPR) * 8;
        float f[8 * DIM];
        if (r < nrows) {
            const float4* s = reinterpret_cast<const float4*>(xt + (size_t)r * CH + m0 * DIM);
            #pragma unroll
            for (int q = 0; q < 2 * DIM; q++) {
                float4 v = s[q];
                f[4*q] = v.x; f[4*q+1] = v.y; f[4*q+2] = v.z; f[4*q+3] = v.w;
            }
        } else {
            #pragma unroll
            for (int q = 0; q < 8 * DIM; q++) f[q] = 0.f;
        }
        #pragma unroll
        for (int i = 0; i < DIM; i++) {
            uint32_t hv[4];
            #pragma unroll
            for (int q = 0; q < 4; q++)
                hv[q] = packh(f[(2*q) * DIM + i], f[(2*q+1) * DIM + i]);
            const unsigned ab = sbase + (unsigned)((r * DIM + i) * LD + m0) * 2u;
            sts128(ab, hv[0], hv[1], hv[2], hv[3]);
        }
    }
    __syncthreads();

    const int l  = tid & 31;
    const int wp = tid >> 5;
    const int wm = wp % WMG;               // M-group
    const int nh = wp / WMG;               // N-group

    const unsigned a_lane = ((l & 15) * LD + ((l >> 4) << 3)) * 2u;
    const uint2* wfrag = d_wf + (size_t)g * SEG_U2 + IOFF2
                       + (size_t)(nh * NBW) * KS * 32 + l;

    float acc[WM][NBW][4];
    #pragma unroll
    for (int mt = 0; mt < WM; mt++)
        #pragma unroll
        for (int nb = 0; nb < NBW; nb++)
            #pragma unroll
            for (int q = 0; q < 4; q++) acc[mt][nb][q] = 0.f;

    // ---- mainloop, B fragments double-buffered ----
    uint2 bf[2][NBW];
    #pragma unroll
    for (int nb = 0; nb < NBW; nb++)
        bf[0][nb] = __ldg(&wfrag[(nb * KS) * 32]);
    for (int ks = 0; ks < KS; ks++) {
        const int cur = ks & 1;
        if (ks + 1 < KS) {
            #pragma unroll
            for (int nb = 0; nb < NBW; nb++)
                bf[cur ^ 1][nb] = __ldg(&wfrag[(nb * KS + ks + 1) * 32]);
        }
        #pragma unroll
        for (int mt = 0; mt < WM; mt++) {
            const unsigned ab = sbase
                + (unsigned)(((wm * WM + mt) * 16) * LD) * 2u
                + (unsigned)ks * 32u + a_lane;
            uint32_t ah[4];
            ldsm4(ah, ab);
            #pragma unroll
            for (int nb = 0; nb < NBW; nb++)
                mma_f16(acc[mt][nb], ah, bf[cur][nb].x, bf[cur][nb].y);
        }
    }

    // ---- epilogue ----
    if (DIM == 1) {
        float* yt = y + (size_t)row0 * CH;
        #pragma unroll
        for (int mt = 0; mt < WM; mt++) {
            const int mrow0 = (wm * WM + mt) * 16 + (l >> 2);
            #pragma unroll
            for (int nb = 0; nb < NBW; nb++) {
                const int n0 = nh * (MUL / WNG) + nb * 8 + (l & 3) * 2;
                #pragma unroll
                for (int rr = 0; rr < 2; rr++) {
                    const int r = mrow0 + rr * 8;
                    if (r < nrows)
                        *reinterpret_cast<float2*>(&yt[(size_t)r * CH + n0]) =
                            make_float2(acc[mt][nb][rr * 2], acc[mt][nb][rr * 2 + 1]);
                }
            }
        }
    } else {
        // bounce through smem in two half-tile passes (reusing A region)
        float* yt = y + (size_t)row0 * CH;
        constexpr int HROWS = 32 * DIM;    // rowp span per half
        constexpr int CH4 = CH / 4;
        __syncthreads();                    // all ldsm reads complete
        #pragma unroll
        for (int h = 0; h < 2; h++) {
            if (wm / (WMG / 2) == h) {
                #pragma unroll
                for (int mt = 0; mt < WM; mt++) {
                    const int mrow0 = (wm * WM + mt) * 16 + (l >> 2) - h * HROWS;
                    #pragma unroll
                    for (int nb = 0; nb < NBW; nb++) {
                        const int n0 = nh * (MUL / WNG) + nb * 8 + (l & 3) * 2;
                        #pragma unroll
                        for (int rr = 0; rr < 2; rr++)
                            *reinterpret_cast<float2*>(
                                &Cs[(mrow0 + rr * 8) * LDC + n0]) =
                                make_float2(acc[mt][nb][rr * 2],
                                            acc[mt][nb][rr * 2 + 1]);
                    }
                }
            }
            __syncthreads();
            for (int e = tid; e < 32 * CH4; e += TPB) {
                const int rl = e / CH4;
                const int c0 = (e - rl * CH4) * 4;
                const int r  = h * 32 + rl;
                if (r < nrows) {
                    float v[4];
                    #pragma unroll
                    for (int j = 0; j < 4; j++) {
                        const int c = c0 + j;
                        const int o = c / DIM;
                        const int i = c - o * DIM;
                        v[j] = Cs[(rl * DIM + i) * LDC + o];
                    }
                    *reinterpret_cast<float4*>(&yt[(size_t)r * CH + c0]) =
                        make_float4(v[0], v[1], v[2], v[3]);
                }
            }
            if (h == 0) __syncthreads();
        }
    }
}

// smem: max over {A halfs, C floats}:
//   A: irrep0 64*136*2=17408; irrep1 192*72*2=27648 (max); irrep2 320*40*2=25600
//   C (half): irrep1 96*66*4=25344; irrep2 160*34*4=21760
#define SMEM_BYTES 27648

__global__ __launch_bounds__(TPB, 3)
void lin_main(const float* __restrict__ x0, const float* __restrict__ x1,
              const float* __restrict__ x2, float* __restrict__ out) {
    __shared__ __align__(16) char smraw[SMEM_BYTES];
    const int b    = blockIdx.x;
    const int irr  = b % 3;                // interleave heavy/light tiles
    const int tile = b / 3;
    if (tile >= d_ntiles) return;
    if (irr == 0) {
        run_irrep<128, 1, 0,    2, 4>(x0, out, tile, smraw);
    } else if (irr == 1) {
        run_irrep<64, 3, 4096,  4, 2>(x1, out + (size_t)NELEM * 128, tile, smraw);
    } else {
        run_irrep<32, 5, 5120,  4, 2>(x2, out + (size_t)NELEM * (128 + 192), tile, smraw);
    }
}

extern "C" void kernel_launch(void* const* d_in, const int* in_sizes, int n_in,
                              void* d_out, int out_size) {
    const float* x0     = (const float*)d_in[0];
    const float* x1     = (const float*)d_in[1];
    const float* x2     = (const float*)d_in[2];
    const float* w      = (const float*)d_in[3];
    const int*   counts = (const int*)d_in[4];
    float*       out    = (float*)d_out;

    pre_kernel<<<4 * NSEG + 1, 256>>>(counts, w);
    lin_main<<<3 * MAX_TILES, TPB>>>(x0, x1, x2, out);
}